// round 9
// baseline (speedup 1.0000x reference)
#include <cuda_runtime.h>
#include <cstdint>

// Router: logits = x[8192,4096] @ kernel[4096,64]; top-8 per token; softmax over top-8.
// out (fp32): [0 .. T*8) = weights, [T*8 .. 2*T*8) = expert indices (as float)
//
// Physical split-K(8): pass1 computes per-slab partials (sequential fp32, ascending kk
// within each 512-K slab); pass2 folds partials in ascending slab order, then
// top-8 + softmax. Accumulation order replicates the reference — DO NOT CHANGE.
//
// Pass1 shape: 1024 CTAs x 64 thr, 7 CTAs/SM (single wave, no tail).
//   x: 2-stage cp.async double buffer (1-chunk lead)
//   k: register prefetch (LDG during previous chunk's compute) + STS, single smem buffer

#define T_TOK 8192
#define D_DIM 4096
#define E_EXP 64
#define NSLAB 8
#define SLABK 512
#define TT    64      // tokens per pass1 CTA
#define KC    32      // K-chunk
#define LDK   72      // k-tile row stride (floats), phase-split (conflict-free)
#define XTILE (TT * KC)          // 2048 floats per x stage
#define KTILE (KC * LDK)         // 2304 floats (single buffer)

#define TT2   8       // tokens per pass2 CTA

typedef unsigned long long u64;

__device__ float g_partial[NSLAB * T_TOK * E_EXP];   // 16.8 MB scratch

__device__ __forceinline__ u64 ffma2(u64 a, u64 b, u64 c) {
    u64 d;
    asm("fma.rn.f32x2 %0, %1, %2, %3;" : "=l"(d) : "l"(a), "l"(b), "l"(c));
    return d;
}
__device__ __forceinline__ u64 bcast2(float x) {
    u64 r;
    asm("mov.b64 %0, {%1, %1};" : "=l"(r) : "f"(x));
    return r;
}
__device__ __forceinline__ void cp16(uint32_t smem_addr, const void* gptr) {
    asm volatile("cp.async.cg.shared.global [%0], [%1], 16;" :: "r"(smem_addr), "l"(gptr));
}
__device__ __forceinline__ void cp_commit() { asm volatile("cp.async.commit_group;"); }
__device__ __forceinline__ void cp_wait1()  { asm volatile("cp.async.wait_group 1;"); }
__device__ __forceinline__ void cp_wait0()  { asm volatile("cp.async.wait_group 0;"); }

// ============================ PASS 1: slab GEMM ============================
// grid (128 t-blocks, 8 slabs) = 1024 CTAs, 64 threads, 7 CTAs/SM => single wave.
// Thread tile: 8 rows x 8 experts.
__global__ __launch_bounds__(64, 7) void slab_gemm_kernel(
    const float* __restrict__ x,
    const float* __restrict__ ker)
{
    __shared__ float sm[2 * XTILE + KTILE];   // 25.6 KB

    const int tid  = threadIdx.x;
    const int tx   = tid & 7;            // e-group: e0 = tx*8
    const int ty   = tid >> 3;           // 0..7 -> rows ty + 8*i
    const int e0   = tx * 8;
    const int koff = e0 + ((tx >= 4) ? 4 : 0);
    const int tb   = blockIdx.x * TT;
    const int k0   = blockIdx.y * SLABK;

    const uint32_t smb  = (uint32_t)__cvta_generic_to_shared(sm);
    const uint32_t ksmb = smb + (uint32_t)(2 * XTILE) * 4u;

    // k load/store thread mapping (coalesced LDG, phase-split STS)
    const int ke4  = tid & 15;
    const int kdk0 = tid >> 4;                      // 0..3
    const int kofs = ke4 * 4 + ((ke4 >= 8) ? 4 : 0);

    u64 acc[8][4];
#pragma unroll
    for (int i = 0; i < 8; i++)
#pragma unroll
        for (int j = 0; j < 4; j++) acc[i][j] = 0ull;

    auto load_x = [&](int c) {                      // cp.async x chunk -> stage c&1
        uint32_t base = smb + (uint32_t)((c & 1) * XTILE) * 4u;
#pragma unroll
        for (int j = 0; j < 8; j++) {
            int t = 8 * j + ty;                     // row
            uint32_t dst = base + (uint32_t)(t * KC + ((tx ^ ty) << 2)) * 4u;
            const float* src = x + (size_t)(tb + t) * D_DIM + k0 + c * KC + tx * 4;
            cp16(dst, src);
        }
        cp_commit();
    };

    float4 kreg[8];
    auto ldg_k = [&](int c) {                       // k chunk -> registers
        const float4* kg = reinterpret_cast<const float4*>(
            ker + (size_t)(k0 + c * KC) * E_EXP);
#pragma unroll
        for (int j = 0; j < 8; j++)
            kreg[j] = kg[(size_t)(4 * j + kdk0) * (E_EXP / 4) + ke4];
    };
    auto sts_k = [&]() {                            // registers -> k smem (phase-split)
#pragma unroll
        for (int j = 0; j < 8; j++) {
            uint32_t dst = ksmb + (uint32_t)((4 * j + kdk0) * LDK + kofs) * 4u;
            asm volatile("st.shared.v4.f32 [%0], {%1,%2,%3,%4};"
                         :: "r"(dst), "f"(kreg[j].x), "f"(kreg[j].y),
                            "f"(kreg[j].z), "f"(kreg[j].w));
        }
    };

    // prologue
    load_x(0);
    ldg_k(0);

    const int nChunks = SLABK / KC;   // 16
    for (int c = 0; c < nChunks; c++) {
        __syncthreads();              // compute c-1 done (k smem + x stage (c+1)&1 free)
        sts_k();                      // k(c) regs -> smem
        if (c + 1 < nChunks) { load_x(c + 1); ldg_k(c + 1); cp_wait1(); }
        else                 { cp_wait0(); }
        __syncthreads();              // k(c) visible; x(c) arrived

        const float* xb_ = sm + (c & 1) * XTILE;
        const float* kb_ = sm + 2 * XTILE;

#pragma unroll
        for (int c4 = 0; c4 < KC / 4; c4++) {
            const int ch = ((c4 ^ ty) << 2) & 31;   // chunk swizzle (matches (tx^ty) store)
            float4 xv[8];
#pragma unroll
            for (int i = 0; i < 8; i++)
                xv[i] = *reinterpret_cast<const float4*>(xb_ + (ty + 8 * i) * KC + ch);
#pragma unroll
            for (int q = 0; q < 4; q++) {
                const int kk = c4 * 4 + q;
                ulonglong2 ka = *reinterpret_cast<const ulonglong2*>(kb_ + kk * LDK + koff);
                ulonglong2 kc = *reinterpret_cast<const ulonglong2*>(kb_ + kk * LDK + koff + 4);
#pragma unroll
                for (int i = 0; i < 8; i++) {
                    float fx = (q == 0) ? xv[i].x : (q == 1) ? xv[i].y
                             : (q == 2) ? xv[i].z : xv[i].w;
                    u64 xp = bcast2(fx);
                    acc[i][0] = ffma2(xp, ka.x, acc[i][0]);
                    acc[i][1] = ffma2(xp, ka.y, acc[i][1]);
                    acc[i][2] = ffma2(xp, kc.x, acc[i][2]);
                    acc[i][3] = ffma2(xp, kc.y, acc[i][3]);
                }
            }
        }
    }

    float* pout = g_partial + (size_t)blockIdx.y * T_TOK * E_EXP;
#pragma unroll
    for (int i = 0; i < 8; i++) {
        int t = tb + ty + 8 * i;
        float* row = pout + (size_t)t * E_EXP + e0;
        *reinterpret_cast<float4*>(row)     = *reinterpret_cast<float4*>(&acc[i][0]);
        *reinterpret_cast<float4*>(row + 4) = *reinterpret_cast<float4*>(&acc[i][2]);
    }
}

// ====================== PASS 2: fold + top-8 + softmax ======================
// grid = 1024 (8 tokens per CTA), 256 threads (R7 config: fastest measured).
__global__ __launch_bounds__(256) void fold_topk_kernel(
    float* __restrict__ out,
    int half)
{
    __shared__ float lg[TT2 * E_EXP];   // 2 KB

    const int tid = threadIdx.x;
    const int tb  = blockIdx.x * TT2;

    // ---- fold: threads 0..127, one (token, e-quad) each; ascending slab order ----
    if (tid < TT2 * (E_EXP / 4)) {
        const int e4 = tid & 15;
        const int t  = tid >> 4;
        const float* p = g_partial + (size_t)(tb + t) * E_EXP + e4 * 4;

        float4 v[NSLAB];
#pragma unroll
        for (int s = 0; s < NSLAB; s++)
            v[s] = *reinterpret_cast<const float4*>(p + (size_t)s * T_TOK * E_EXP);

        float4 a = v[0];
#pragma unroll
        for (int s = 1; s < NSLAB; s++) {
            a.x += v[s].x; a.y += v[s].y; a.z += v[s].z; a.w += v[s].w;
        }
        *reinterpret_cast<float4*>(&lg[t * E_EXP + e4 * 4]) = a;
    }
    __syncthreads();

    // ---- top-8 + softmax: one warp per token ----
    const int w    = tid >> 5;
    const int lane = tid & 31;
    const unsigned FULL = 0xffffffffu;

    const int t = w;
    float v0 = lg[t * E_EXP + lane];
    float v1 = lg[t * E_EXP + 32 + lane];

    float vals[8];
    int   inds[8];
#pragma unroll
    for (int k = 0; k < 8; k++) {
        float bv; int bi;
        if (v0 >= v1) { bv = v0; bi = lane; }
        else          { bv = v1; bi = lane + 32; }
#pragma unroll
        for (int off = 16; off > 0; off >>= 1) {
            float ov = __shfl_xor_sync(FULL, bv, off);
            int   oi = __shfl_xor_sync(FULL, bi, off);
            if (ov > bv || (ov == bv && oi < bi)) { bv = ov; bi = oi; }
        }
        vals[k] = bv;
        inds[k] = bi;
        if (bi == lane)           v0 = -3.4e38f;
        else if (bi == lane + 32) v1 = -3.4e38f;
    }

    if (lane == 0) {
        float m = vals[0];
        float ws[8];
        float ssum = 0.0f;
#pragma unroll
        for (int k = 0; k < 8; k++) { ws[k] = expf(vals[k] - m); ssum += ws[k]; }
        float r = 1.0f / ssum;
        int tg = tb + t;
#pragma unroll
        for (int k = 0; k < 8; k++) {
            out[tg * 8 + k]        = ws[k] * r;
            out[half + tg * 8 + k] = (float)inds[k];
        }
    }
}

extern "C" void kernel_launch(void* const* d_in, const int* in_sizes, int n_in,
                              void* d_out, int out_size) {
    const float* x   = (const float*)d_in[0];
    const float* ker = (const float*)d_in[1];
    float* out = (float*)d_out;
    int half = out_size / 2;

    dim3 grid1(T_TOK / TT, NSLAB);
    slab_gemm_kernel<<<grid1, 64>>>(x, ker);
    fold_topk_kernel<<<T_TOK / TT2, 256>>>(out, half);
}

// round 10
// speedup vs baseline: 1.2241x; 1.2241x over previous
#include <cuda_runtime.h>
#include <cstdint>

// Router: logits = x[8192,4096] @ kernel[4096,64]; top-8 per token; softmax over top-8.
// out (fp32): [0 .. T*8) = weights, [T*8 .. 2*T*8) = expert indices (as float)
//
// Physical split-K(8): pass1 computes per-slab partials (sequential fp32, ascending kk
// within each 512-K slab); pass2 folds partials in ascending slab order, then
// top-8 + softmax. Accumulation order replicates the reference — DO NOT CHANGE.
//
// Pass1: 256 t-blocks x 8 slabs = 2048 CTAs, 64 thr, 8 CTAs/SM (fine-grain drain).

#define T_TOK 8192
#define D_DIM 4096
#define E_EXP 64
#define NSLAB 8
#define SLABK 512
#define TT    32      // tokens per pass1 CTA
#define KC    32      // K-chunk per stage
#define LDK   72      // k-tile row stride (floats), phase-split (conflict-free)
#define XTILE (TT * KC)          // 1024 floats
#define KTILE (KC * LDK)         // 2304 floats
#define STAGE (XTILE + KTILE)    // 3328 floats = 13.3 KB

#define TT2   8       // tokens per pass2 CTA

typedef unsigned long long u64;

__device__ float g_partial[NSLAB * T_TOK * E_EXP];   // 16.8 MB scratch

__device__ __forceinline__ u64 ffma2(u64 a, u64 b, u64 c) {
    u64 d;
    asm("fma.rn.f32x2 %0, %1, %2, %3;" : "=l"(d) : "l"(a), "l"(b), "l"(c));
    return d;
}
__device__ __forceinline__ u64 bcast2(float x) {
    u64 r;
    asm("mov.b64 %0, {%1, %1};" : "=l"(r) : "f"(x));
    return r;
}
__device__ __forceinline__ void cp16(uint32_t smem_addr, const void* gptr) {
    asm volatile("cp.async.cg.shared.global [%0], [%1], 16;" :: "r"(smem_addr), "l"(gptr));
}
__device__ __forceinline__ void cp_commit() { asm volatile("cp.async.commit_group;"); }
__device__ __forceinline__ void cp_wait1()  { asm volatile("cp.async.wait_group 1;"); }
__device__ __forceinline__ void cp_wait0()  { asm volatile("cp.async.wait_group 0;"); }

// ============================ PASS 1: slab GEMM ============================
// grid (256 t-blocks, 8 slabs) = 2048 CTAs, 64 threads, 8 CTAs/SM.
// Thread tile: 4 rows x 8 experts. Pipeline identical to R7 (proven fastest).
__global__ __launch_bounds__(64, 8) void slab_gemm_kernel(
    const float* __restrict__ x,
    const float* __restrict__ ker)
{
    __shared__ float sm[2 * STAGE];   // 26.6 KB

    const int tid  = threadIdx.x;
    const int tx   = tid & 7;            // e-group: e0 = tx*8
    const int ty   = tid >> 3;           // 0..7 -> rows ty + 8*i (i=0..3)
    const int e0   = tx * 8;
    const int koff = e0 + ((tx >= 4) ? 4 : 0);
    const int tb   = blockIdx.x * TT;
    const int k0   = blockIdx.y * SLABK;

    const uint32_t smb = (uint32_t)__cvta_generic_to_shared(sm);

    u64 acc[4][4];
#pragma unroll
    for (int i = 0; i < 4; i++)
#pragma unroll
        for (int j = 0; j < 4; j++) acc[i][j] = 0ull;

    auto load_chunk = [&](int c, int s) {
        uint32_t base = smb + (uint32_t)(s * STAGE) * 4u;
        // x: 32 rows x 32 fl = 256 float4 / 64 thr = 4 each
#pragma unroll
        for (int j = 0; j < 4; j++) {
            int f  = j * 64 + tid;
            int d4 = f & 7;                           // chunk within row (8 per row)
            int t  = f >> 3;                          // 0..31
            uint32_t dst = base + (uint32_t)(t * KC + ((d4 ^ (t & 7)) << 2)) * 4u;
            const float* src = x + (size_t)(tb + t) * D_DIM + k0 + c * KC + d4 * 4;
            cp16(dst, src);
        }
        // k: 32 kk x 64 e = 512 float4 / 64 thr = 8 each (phase-split rows)
        {
            int e4 = tid & 15;
            int ofs = e4 * 4 + ((e4 >= 8) ? 4 : 0);
#pragma unroll
            for (int j = 0; j < 8; j++) {
                int dk = 4 * j + (tid >> 4);
                uint32_t dst = base + (uint32_t)(XTILE + dk * LDK + ofs) * 4u;
                const float* src = ker + (size_t)(k0 + c * KC + dk) * E_EXP + e4 * 4;
                cp16(dst, src);
            }
        }
        cp_commit();
    };

    load_chunk(0, 0);
    load_chunk(1, 1);

    const int nChunks = SLABK / KC;   // 16
    for (int c = 0; c < nChunks; c++) {
        if (c == nChunks - 1) cp_wait0(); else cp_wait1();
        __syncthreads();

        const int b = c & 1;
        const float* xb_ = sm + b * STAGE;
        const float* kb_ = sm + b * STAGE + XTILE;

#pragma unroll
        for (int c4 = 0; c4 < KC / 4; c4++) {
            const int ch = ((c4 ^ ty) << 2);
            float4 xv[4];
#pragma unroll
            for (int i = 0; i < 4; i++)
                xv[i] = *reinterpret_cast<const float4*>(xb_ + (ty + 8 * i) * KC + ch);
#pragma unroll
            for (int q = 0; q < 4; q++) {
                const int kk = c4 * 4 + q;
                ulonglong2 ka = *reinterpret_cast<const ulonglong2*>(kb_ + kk * LDK + koff);
                ulonglong2 kc = *reinterpret_cast<const ulonglong2*>(kb_ + kk * LDK + koff + 4);
#pragma unroll
                for (int i = 0; i < 4; i++) {
                    float fx = (q == 0) ? xv[i].x : (q == 1) ? xv[i].y
                             : (q == 2) ? xv[i].z : xv[i].w;
                    u64 xp = bcast2(fx);
                    acc[i][0] = ffma2(xp, ka.x, acc[i][0]);
                    acc[i][1] = ffma2(xp, ka.y, acc[i][1]);
                    acc[i][2] = ffma2(xp, kc.x, acc[i][2]);
                    acc[i][3] = ffma2(xp, kc.y, acc[i][3]);
                }
            }
        }
        __syncthreads();   // all reads of buffer b done before refill
        if (c + 2 < nChunks) load_chunk(c + 2, b);
    }

    float* pout = g_partial + (size_t)blockIdx.y * T_TOK * E_EXP;
#pragma unroll
    for (int i = 0; i < 4; i++) {
        int t = tb + ty + 8 * i;
        float* row = pout + (size_t)t * E_EXP + e0;
        *reinterpret_cast<float4*>(row)     = *reinterpret_cast<float4*>(&acc[i][0]);
        *reinterpret_cast<float4*>(row + 4) = *reinterpret_cast<float4*>(&acc[i][2]);
    }
}

// ====================== PASS 2: fold + top-8 + softmax ======================
// grid = 1024 (8 tokens per CTA), 256 threads (measured fastest config).
__global__ __launch_bounds__(256) void fold_topk_kernel(
    float* __restrict__ out,
    int half)
{
    __shared__ float lg[TT2 * E_EXP];   // 2 KB

    const int tid = threadIdx.x;
    const int tb  = blockIdx.x * TT2;

    // ---- fold: threads 0..127, one (token, e-quad) each; ascending slab order ----
    if (tid < TT2 * (E_EXP / 4)) {
        const int e4 = tid & 15;
        const int t  = tid >> 4;
        const float* p = g_partial + (size_t)(tb + t) * E_EXP + e4 * 4;

        float4 v[NSLAB];
#pragma unroll
        for (int s = 0; s < NSLAB; s++)
            v[s] = *reinterpret_cast<const float4*>(p + (size_t)s * T_TOK * E_EXP);

        float4 a = v[0];
#pragma unroll
        for (int s = 1; s < NSLAB; s++) {
            a.x += v[s].x; a.y += v[s].y; a.z += v[s].z; a.w += v[s].w;
        }
        *reinterpret_cast<float4*>(&lg[t * E_EXP + e4 * 4]) = a;
    }
    __syncthreads();

    // ---- top-8 + softmax: one warp per token ----
    const int w    = tid >> 5;
    const int lane = tid & 31;
    const unsigned FULL = 0xffffffffu;

    const int t = w;
    float v0 = lg[t * E_EXP + lane];
    float v1 = lg[t * E_EXP + 32 + lane];

    float vals[8];
    int   inds[8];
#pragma unroll
    for (int k = 0; k < 8; k++) {
        float bv; int bi;
        if (v0 >= v1) { bv = v0; bi = lane; }
        else          { bv = v1; bi = lane + 32; }
#pragma unroll
        for (int off = 16; off > 0; off >>= 1) {
            float ov = __shfl_xor_sync(FULL, bv, off);
            int   oi = __shfl_xor_sync(FULL, bi, off);
            if (ov > bv || (ov == bv && oi < bi)) { bv = ov; bi = oi; }
        }
        vals[k] = bv;
        inds[k] = bi;
        if (bi == lane)           v0 = -3.4e38f;
        else if (bi == lane + 32) v1 = -3.4e38f;
    }

    if (lane == 0) {
        float m = vals[0];
        float ws[8];
        float ssum = 0.0f;
#pragma unroll
        for (int k = 0; k < 8; k++) { ws[k] = expf(vals[k] - m); ssum += ws[k]; }
        float r = 1.0f / ssum;
        int tg = tb + t;
#pragma unroll
        for (int k = 0; k < 8; k++) {
            out[tg * 8 + k]        = ws[k] * r;
            out[half + tg * 8 + k] = (float)inds[k];
        }
    }
}

extern "C" void kernel_launch(void* const* d_in, const int* in_sizes, int n_in,
                              void* d_out, int out_size) {
    const float* x   = (const float*)d_in[0];
    const float* ker = (const float*)d_in[1];
    float* out = (float*)d_out;
    int half = out_size / 2;

    dim3 grid1(T_TOK / TT, NSLAB);
    slab_gemm_kernel<<<grid1, 64>>>(x, ker);
    fold_topk_kernel<<<T_TOK / TT2, 256>>>(out, half);
}

// round 13
// speedup vs baseline: 1.2378x; 1.0112x over previous
#include <cuda_runtime.h>
#include <cstdint>

// Router: logits = x[8192,4096] @ kernel[4096,64]; top-8 per token; softmax over top-8.
// out (fp32): [0 .. T*8) = weights, [T*8 .. 2*T*8) = expert indices (as float)
//
// Physical split-K(8): pass1 computes per-slab partials (sequential fp32, ascending kk
// within each 512-K slab); pass2 folds partials in ascending slab order, then
// top-8 + softmax. Accumulation order replicates the reference — DO NOT CHANGE.
//
// Pass1: 2048 CTAs x 64 thr, 8 CTAs/SM, single-sync 2-stage cp.async pipeline.
// (No L2 policy instructions — they trap on sm_103a.)

#define T_TOK 8192
#define D_DIM 4096
#define E_EXP 64
#define NSLAB 8
#define SLABK 512
#define TT    32      // tokens per pass1 CTA
#define KC    32      // K-chunk per stage
#define LDK   72      // k-tile row stride (floats), phase-split (conflict-free)
#define XTILE (TT * KC)          // 1024 floats
#define KTILE (KC * LDK)         // 2304 floats
#define STAGE (XTILE + KTILE)    // 3328 floats = 13.3 KB

#define TT2   8       // tokens per pass2 CTA

typedef unsigned long long u64;

__device__ float g_partial[NSLAB * T_TOK * E_EXP];   // 16.8 MB scratch

__device__ __forceinline__ u64 ffma2(u64 a, u64 b, u64 c) {
    u64 d;
    asm("fma.rn.f32x2 %0, %1, %2, %3;" : "=l"(d) : "l"(a), "l"(b), "l"(c));
    return d;
}
__device__ __forceinline__ u64 bcast2(float x) {
    u64 r;
    asm("mov.b64 %0, {%1, %1};" : "=l"(r) : "f"(x));
    return r;
}
__device__ __forceinline__ void cp16(uint32_t smem_addr, const void* gptr) {
    asm volatile("cp.async.cg.shared.global [%0], [%1], 16;" :: "r"(smem_addr), "l"(gptr));
}
__device__ __forceinline__ void cp_commit() { asm volatile("cp.async.commit_group;"); }
__device__ __forceinline__ void cp_wait0()  { asm volatile("cp.async.wait_group 0;"); }

// ============================ PASS 1: slab GEMM ============================
// grid (256 t-blocks, 8 slabs) = 2048 CTAs, 64 threads, 8 CTAs/SM.
// Thread tile: 4 rows x 8 experts.
__global__ __launch_bounds__(64, 8) void slab_gemm_kernel(
    const float* __restrict__ x,
    const float* __restrict__ ker)
{
    __shared__ float sm[2 * STAGE];   // 26.6 KB

    const int tid  = threadIdx.x;
    const int tx   = tid & 7;            // e-group: e0 = tx*8
    const int ty   = tid >> 3;           // 0..7 -> rows ty + 8*i (i=0..3)
    const int e0   = tx * 8;
    const int koff = e0 + ((tx >= 4) ? 4 : 0);
    const int tb   = blockIdx.x * TT;
    const int k0   = blockIdx.y * SLABK;

    const uint32_t smb = (uint32_t)__cvta_generic_to_shared(sm);

    u64 acc[4][4];
#pragma unroll
    for (int i = 0; i < 4; i++)
#pragma unroll
        for (int j = 0; j < 4; j++) acc[i][j] = 0ull;

    auto load_chunk = [&](int c) {
        uint32_t base = smb + (uint32_t)((c & 1) * STAGE) * 4u;
        // x: 32 rows x 32 fl = 256 float4 / 64 thr = 4 each
#pragma unroll
        for (int j = 0; j < 4; j++) {
            int f  = j * 64 + tid;
            int d4 = f & 7;                           // chunk within row (8 per row)
            int t  = f >> 3;                          // 0..31
            uint32_t dst = base + (uint32_t)(t * KC + ((d4 ^ (t & 7)) << 2)) * 4u;
            const float* src = x + (size_t)(tb + t) * D_DIM + k0 + c * KC + d4 * 4;
            cp16(dst, src);
        }
        // k: 32 kk x 64 e = 512 float4 / 64 thr = 8 each (phase-split rows)
        {
            int e4 = tid & 15;
            int ofs = e4 * 4 + ((e4 >= 8) ? 4 : 0);
#pragma unroll
            for (int j = 0; j < 8; j++) {
                int dk = 4 * j + (tid >> 4);
                uint32_t dst = base + (uint32_t)(XTILE + dk * LDK + ofs) * 4u;
                const float* src = ker + (size_t)(k0 + c * KC + dk) * E_EXP + e4 * 4;
                cp16(dst, src);
            }
        }
        cp_commit();
    };

    load_chunk(0);

    const int nChunks = SLABK / KC;   // 16
    for (int c = 0; c < nChunks; c++) {
        cp_wait0();                   // load(c) complete (issued last iter; overlapped)
        __syncthreads();              // data visible; prior readers of buffer (c&1) done

        if (c + 1 < nChunks) load_chunk(c + 1);

        const int b = c & 1;
        const float* xb_ = sm + b * STAGE;
        const float* kb_ = sm + b * STAGE + XTILE;

#pragma unroll
        for (int c4 = 0; c4 < KC / 4; c4++) {
            const int ch = ((c4 ^ ty) << 2);
            float4 xv[4];
#pragma unroll
            for (int i = 0; i < 4; i++)
                xv[i] = *reinterpret_cast<const float4*>(xb_ + (ty + 8 * i) * KC + ch);
#pragma unroll
            for (int q = 0; q < 4; q++) {
                const int kk = c4 * 4 + q;
                ulonglong2 ka = *reinterpret_cast<const ulonglong2*>(kb_ + kk * LDK + koff);
                ulonglong2 kc = *reinterpret_cast<const ulonglong2*>(kb_ + kk * LDK + koff + 4);
#pragma unroll
                for (int i = 0; i < 4; i++) {
                    float fx = (q == 0) ? xv[i].x : (q == 1) ? xv[i].y
                             : (q == 2) ? xv[i].z : xv[i].w;
                    u64 xp = bcast2(fx);
                    acc[i][0] = ffma2(xp, ka.x, acc[i][0]);
                    acc[i][1] = ffma2(xp, ka.y, acc[i][1]);
                    acc[i][2] = ffma2(xp, kc.x, acc[i][2]);
                    acc[i][3] = ffma2(xp, kc.y, acc[i][3]);
                }
            }
        }
    }

    float* pout = g_partial + (size_t)blockIdx.y * T_TOK * E_EXP;
#pragma unroll
    for (int i = 0; i < 4; i++) {
        int t = tb + ty + 8 * i;
        float* row = pout + (size_t)t * E_EXP + e0;
        *reinterpret_cast<float4*>(row)     = *reinterpret_cast<float4*>(&acc[i][0]);
        *reinterpret_cast<float4*>(row + 4) = *reinterpret_cast<float4*>(&acc[i][2]);
    }
}

// ====================== PASS 2: fold + top-8 + softmax ======================
// grid = 1024 (8 tokens per CTA), 256 threads.
__global__ __launch_bounds__(256) void fold_topk_kernel(
    float* __restrict__ out,
    int half)
{
    __shared__ float lg[TT2 * E_EXP];   // 2 KB

    const int tid = threadIdx.x;
    const int tb  = blockIdx.x * TT2;

    // ---- fold: threads 0..127, one (token, e-quad) each; ascending slab order ----
    if (tid < TT2 * (E_EXP / 4)) {
        const int e4 = tid & 15;
        const int t  = tid >> 4;
        const float* p = g_partial + (size_t)(tb + t) * E_EXP + e4 * 4;

        float4 v[NSLAB];
#pragma unroll
        for (int s = 0; s < NSLAB; s++)
            v[s] = *reinterpret_cast<const float4*>(p + (size_t)s * T_TOK * E_EXP);

        float4 a = v[0];
#pragma unroll
        for (int s = 1; s < NSLAB; s++) {
            a.x += v[s].x; a.y += v[s].y; a.z += v[s].z; a.w += v[s].w;
        }
        *reinterpret_cast<float4*>(&lg[t * E_EXP + e4 * 4]) = a;
    }
    __syncthreads();

    // ---- top-8 + softmax: one warp per token ----
    const int w    = tid >> 5;
    const int lane = tid & 31;
    const unsigned FULL = 0xffffffffu;

    const int t = w;
    float v0 = lg[t * E_EXP + lane];
    float v1 = lg[t * E_EXP + 32 + lane];

    float vals[8];
    int   inds[8];
#pragma unroll
    for (int k = 0; k < 8; k++) {
        float bv; int bi;
        if (v0 >= v1) { bv = v0; bi = lane; }
        else          { bv = v1; bi = lane + 32; }
#pragma unroll
        for (int off = 16; off > 0; off >>= 1) {
            float ov = __shfl_xor_sync(FULL, bv, off);
            int   oi = __shfl_xor_sync(FULL, bi, off);
            if (ov > bv || (ov == bv && oi < bi)) { bv = ov; bi = oi; }
        }
        vals[k] = bv;
        inds[k] = bi;
        if (bi == lane)           v0 = -3.4e38f;
        else if (bi == lane + 32) v1 = -3.4e38f;
    }

    if (lane == 0) {
        float m = vals[0];
        float ws[8];
        float ssum = 0.0f;
#pragma unroll
        for (int k = 0; k < 8; k++) { ws[k] = expf(vals[k] - m); ssum += ws[k]; }
        float r = 1.0f / ssum;
        int tg = tb + t;
#pragma unroll
        for (int k = 0; k < 8; k++) {
            out[tg * 8 + k]        = ws[k] * r;
            out[half + tg * 8 + k] = (float)inds[k];
        }
    }
}

extern "C" void kernel_launch(void* const* d_in, const int* in_sizes, int n_in,
                              void* d_out, int out_size) {
    const float* x   = (const float*)d_in[0];
    const float* ker = (const float*)d_in[1];
    float* out = (float*)d_out;
    int half = out_size / 2;

    dim3 grid1(T_TOK / TT, NSLAB);
    slab_gemm_kernel<<<grid1, 64>>>(x, ker);
    fold_topk_kernel<<<T_TOK / TT2, 256>>>(out, half);
}

// round 14
// speedup vs baseline: 1.2444x; 1.0053x over previous
#include <cuda_runtime.h>
#include <cstdint>

// Router: logits = x[8192,4096] @ kernel[4096,64]; top-8 per token; softmax over top-8.
// out (fp32): [0 .. T*8) = weights, [T*8 .. 2*T*8) = expert indices (as float)
//
// Physical split-K(8): pass1 computes per-slab partials (sequential fp32, ascending kk
// within each 512-K slab); pass2 folds partials in ascending slab order, then
// top-8 + softmax. Accumulation order replicates the reference — DO NOT CHANGE.
//
// Scratch layout is token-major [t][slab][e] so pass2 reads are fully sequential.

#define T_TOK 8192
#define D_DIM 4096
#define E_EXP 64
#define NSLAB 8
#define SLABK 512
#define TT    32      // tokens per pass1 CTA
#define KC    32      // K-chunk per stage
#define LDK   72      // k-tile row stride (floats), phase-split (conflict-free)
#define XTILE (TT * KC)          // 1024 floats
#define KTILE (KC * LDK)         // 2304 floats
#define STAGE (XTILE + KTILE)    // 3328 floats = 13.3 KB

#define TT2   8       // tokens per pass2 CTA

typedef unsigned long long u64;

__device__ float g_partial[T_TOK * NSLAB * E_EXP];   // [t][slab][e], 16.8 MB

__device__ __forceinline__ u64 ffma2(u64 a, u64 b, u64 c) {
    u64 d;
    asm("fma.rn.f32x2 %0, %1, %2, %3;" : "=l"(d) : "l"(a), "l"(b), "l"(c));
    return d;
}
__device__ __forceinline__ u64 bcast2(float x) {
    u64 r;
    asm("mov.b64 %0, {%1, %1};" : "=l"(r) : "f"(x));
    return r;
}
__device__ __forceinline__ void cp16(uint32_t smem_addr, const void* gptr) {
    asm volatile("cp.async.cg.shared.global [%0], [%1], 16;" :: "r"(smem_addr), "l"(gptr));
}
__device__ __forceinline__ void cp_commit() { asm volatile("cp.async.commit_group;"); }
__device__ __forceinline__ void cp_wait0()  { asm volatile("cp.async.wait_group 0;"); }

// ============================ PASS 1: slab GEMM ============================
// grid (256 t-blocks, 8 slabs) = 2048 CTAs, 64 threads, 8 CTAs/SM.
// Thread tile: 4 rows x 8 experts.
__global__ __launch_bounds__(64, 8) void slab_gemm_kernel(
    const float* __restrict__ x,
    const float* __restrict__ ker)
{
    __shared__ float sm[2 * STAGE];   // 26.6 KB

    const int tid  = threadIdx.x;
    const int tx   = tid & 7;            // e-group: e0 = tx*8
    const int ty   = tid >> 3;           // 0..7 -> rows ty + 8*i (i=0..3)
    const int e0   = tx * 8;
    const int koff = e0 + ((tx >= 4) ? 4 : 0);
    const int tb   = blockIdx.x * TT;
    const int k0   = blockIdx.y * SLABK;

    const uint32_t smb = (uint32_t)__cvta_generic_to_shared(sm);

    u64 acc[4][4];
#pragma unroll
    for (int i = 0; i < 4; i++)
#pragma unroll
        for (int j = 0; j < 4; j++) acc[i][j] = 0ull;

    auto load_chunk = [&](int c) {
        uint32_t base = smb + (uint32_t)((c & 1) * STAGE) * 4u;
        // x: 32 rows x 32 fl = 256 float4 / 64 thr = 4 each
#pragma unroll
        for (int j = 0; j < 4; j++) {
            int f  = j * 64 + tid;
            int d4 = f & 7;                           // chunk within row (8 per row)
            int t  = f >> 3;                          // 0..31
            uint32_t dst = base + (uint32_t)(t * KC + ((d4 ^ (t & 7)) << 2)) * 4u;
            const float* src = x + (size_t)(tb + t) * D_DIM + k0 + c * KC + d4 * 4;
            cp16(dst, src);
        }
        // k: 32 kk x 64 e = 512 float4 / 64 thr = 8 each (phase-split rows)
        {
            int e4 = tid & 15;
            int ofs = e4 * 4 + ((e4 >= 8) ? 4 : 0);
#pragma unroll
            for (int j = 0; j < 8; j++) {
                int dk = 4 * j + (tid >> 4);
                uint32_t dst = base + (uint32_t)(XTILE + dk * LDK + ofs) * 4u;
                const float* src = ker + (size_t)(k0 + c * KC + dk) * E_EXP + e4 * 4;
                cp16(dst, src);
            }
        }
        cp_commit();
    };

    load_chunk(0);

    const int nChunks = SLABK / KC;   // 16
    for (int c = 0; c < nChunks; c++) {
        cp_wait0();                   // load(c) complete (issued last iter; overlapped)
        __syncthreads();              // data visible; prior readers of buffer (c&1) done

        if (c + 1 < nChunks) load_chunk(c + 1);

        const int b = c & 1;
        const float* xb_ = sm + b * STAGE;
        const float* kb_ = sm + b * STAGE + XTILE;

#pragma unroll
        for (int c4 = 0; c4 < KC / 4; c4++) {
            const int ch = ((c4 ^ ty) << 2);
            float4 xv[4];
#pragma unroll
            for (int i = 0; i < 4; i++)
                xv[i] = *reinterpret_cast<const float4*>(xb_ + (ty + 8 * i) * KC + ch);
#pragma unroll
            for (int q = 0; q < 4; q++) {
                const int kk = c4 * 4 + q;
                ulonglong2 ka = *reinterpret_cast<const ulonglong2*>(kb_ + kk * LDK + koff);
                ulonglong2 kc = *reinterpret_cast<const ulonglong2*>(kb_ + kk * LDK + koff + 4);
#pragma unroll
                for (int i = 0; i < 4; i++) {
                    float fx = (q == 0) ? xv[i].x : (q == 1) ? xv[i].y
                             : (q == 2) ? xv[i].z : xv[i].w;
                    u64 xp = bcast2(fx);
                    acc[i][0] = ffma2(xp, ka.x, acc[i][0]);
                    acc[i][1] = ffma2(xp, ka.y, acc[i][1]);
                    acc[i][2] = ffma2(xp, kc.x, acc[i][2]);
                    acc[i][3] = ffma2(xp, kc.y, acc[i][3]);
                }
            }
        }
    }

    // write slab partials, token-major layout [t][slab][e]
    const int slab = blockIdx.y;
#pragma unroll
    for (int i = 0; i < 4; i++) {
        int t = tb + ty + 8 * i;
        float* row = g_partial + ((size_t)t * NSLAB + slab) * E_EXP + e0;
        *reinterpret_cast<float4*>(row)     = *reinterpret_cast<float4*>(&acc[i][0]);
        *reinterpret_cast<float4*>(row + 4) = *reinterpret_cast<float4*>(&acc[i][2]);
    }
}

// ====================== PASS 2: fold + top-8 + softmax ======================
// grid = 1024 (8 tokens per CTA), 256 threads. Each CTA reads one contiguous
// 16 KB block. All 256 threads fold: one (token, e-quad) each, 8 slab quads
// spanning 2 KB, summed in ascending slab order.
__global__ __launch_bounds__(256) void fold_topk_kernel(
    float* __restrict__ out,
    int half)
{
    __shared__ float lg[TT2 * E_EXP];   // 2 KB

    const int tid = threadIdx.x;
    const int tb  = blockIdx.x * TT2;

    // ---- fold ----
    {
        const int e4 = tid & 15;          // e-quad 0..15
        const int t  = tid >> 4;          // token 0..15? no: 256/16 = 16 -> but TT2=8
        // 256 threads, 8 tokens x 16 quads = 128 fold slots -> 2 threads share pattern;
        // use tid<128 mapping but give each thread 1 slot and remaining threads token+8?
        // Simpler: threads 0..127 fold (t = tid>>4 in 0..7), MLP 8 contiguous.
        if (tid < TT2 * (E_EXP / 4)) {
            const float* p = g_partial + ((size_t)(tb + t) * NSLAB) * E_EXP + e4 * 4;
            float4 v[NSLAB];
#pragma unroll
            for (int s = 0; s < NSLAB; s++)
                v[s] = *reinterpret_cast<const float4*>(p + s * E_EXP);
            float4 a = v[0];
#pragma unroll
            for (int s = 1; s < NSLAB; s++) {
                a.x += v[s].x; a.y += v[s].y; a.z += v[s].z; a.w += v[s].w;
            }
            *reinterpret_cast<float4*>(&lg[t * E_EXP + e4 * 4]) = a;
        }
    }
    __syncthreads();

    // ---- top-8 + softmax: one warp per token ----
    const int w    = tid >> 5;
    const int lane = tid & 31;
    const unsigned FULL = 0xffffffffu;

    const int t = w;
    float v0 = lg[t * E_EXP + lane];
    float v1 = lg[t * E_EXP + 32 + lane];

    float vals[8];
    int   inds[8];
#pragma unroll
    for (int k = 0; k < 8; k++) {
        float bv; int bi;
        if (v0 >= v1) { bv = v0; bi = lane; }
        else          { bv = v1; bi = lane + 32; }
#pragma unroll
        for (int off = 16; off > 0; off >>= 1) {
            float ov = __shfl_xor_sync(FULL, bv, off);
            int   oi = __shfl_xor_sync(FULL, bi, off);
            if (ov > bv || (ov == bv && oi < bi)) { bv = ov; bi = oi; }
        }
        vals[k] = bv;
        inds[k] = bi;
        if (bi == lane)           v0 = -3.4e38f;
        else if (bi == lane + 32) v1 = -3.4e38f;
    }

    if (lane == 0) {
        float m = vals[0];
        float ws[8];
        float ssum = 0.0f;
#pragma unroll
        for (int k = 0; k < 8; k++) { ws[k] = expf(vals[k] - m); ssum += ws[k]; }
        float r = 1.0f / ssum;
        int tg = tb + t;
#pragma unroll
        for (int k = 0; k < 8; k++) {
            out[tg * 8 + k]        = ws[k] * r;
            out[half + tg * 8 + k] = (float)inds[k];
        }
    }
}

extern "C" void kernel_launch(void* const* d_in, const int* in_sizes, int n_in,
                              void* d_out, int out_size) {
    const float* x   = (const float*)d_in[0];
    const float* ker = (const float*)d_in[1];
    float* out = (float*)d_out;
    int half = out_size / 2;

    dim3 grid1(T_TOK / TT, NSLAB);
    slab_gemm_kernel<<<grid1, 64>>>(x, ker);
    fold_topk_kernel<<<T_TOK / TT2, 256>>>(out, half);
}